// round 6
// baseline (speedup 1.0000x reference)
#include <cuda_runtime.h>
#include <cuda_fp16.h>
#include <cstdint>
#include <cstddef>

#define NN 50000
#define EE 800000
#define FIN 256
#define HID 128
#define HEADS 4
#define NGRAPH 50
#define NEG_SLOPE 0.2f

// ---------------- scratch (device globals; no allocation allowed) -------------
__device__ __half g_hh[(size_t)NN * HEADS * HID];   // GEMM output (fp16 messages)
__device__ float g_act[(size_t)NN * HEADS * HID];   // aggregated output / next input
__device__ float g_as[NN * HEADS];
__device__ float g_ad[NN * HEADS];
__device__ int   g_deg[NN];
__device__ int   g_rowstart[NN + 1];
__device__ int   g_cursor[NN];
__device__ int   g_csr_src[EE];
__device__ float g_coef[(size_t)EE * HEADS];        // normalized alpha, CSR order
__device__ float g_pool[NGRAPH * HID];
__device__ float g_cnt[NGRAPH];

// ==================== TF32 tensor-core GEMM + fused alpha epilogue ====================
// C[M,N] = A[M,K] @ B[K,N]. C stored as fp16 (messages); alpha dots computed
// from fp32 accumulator fragments (full precision) and atomically accumulated.
// Each 128-col block tile covers exactly one head.

__device__ __forceinline__ float to_tf32(float x) {
    float y;
    asm("cvt.rna.tf32.f32 %0, %1;" : "=f"(y) : "f"(x));
    return y;
}

__global__ __launch_bounds__(256) void tf32_gemm_alpha_kernel(
    const float* __restrict__ A, const float* __restrict__ B, __half* __restrict__ C,
    int M, int K, int N,
    const float* __restrict__ a_src, const float* __restrict__ a_dst,  // [H][HID]
    float* __restrict__ as_out, float* __restrict__ ad_out, int H)
{
    __shared__ __align__(16) float As[128][36];
    __shared__ __align__(16) float Bs[32][136];

    const int tid  = threadIdx.x;
    const int lane = tid & 31;
    const int warp = tid >> 5;
    const int wm = (warp & 1) * 64;
    const int wn = (warp >> 1) * 32;

    const int mBase = blockIdx.y * 128;
    const int nBase = blockIdx.x * 128;

    float c[4][4][4];
#pragma unroll
    for (int mi = 0; mi < 4; mi++)
#pragma unroll
        for (int ni = 0; ni < 4; ni++)
#pragma unroll
            for (int q = 0; q < 4; q++) c[mi][ni][q] = 0.f;

    const int arow = tid >> 3;
    const int acol = (tid & 7) * 4;
    const int brow = tid >> 5;
    const int bcol = (tid & 31) * 4;

    for (int k0 = 0; k0 < K; k0 += 32) {
#pragma unroll
        for (int p = 0; p < 4; p++) {
            int r = arow + p * 32;
            int gr = mBase + r;
            float4 v = make_float4(0.f, 0.f, 0.f, 0.f);
            if (gr < M) v = *(const float4*)&A[(size_t)gr * K + k0 + acol];
            As[r][acol + 0] = to_tf32(v.x);
            As[r][acol + 1] = to_tf32(v.y);
            As[r][acol + 2] = to_tf32(v.z);
            As[r][acol + 3] = to_tf32(v.w);
        }
#pragma unroll
        for (int p = 0; p < 4; p++) {
            int r = brow + p * 8;
            float4 v = *(const float4*)&B[(size_t)(k0 + r) * N + nBase + bcol];
            Bs[r][bcol + 0] = to_tf32(v.x);
            Bs[r][bcol + 1] = to_tf32(v.y);
            Bs[r][bcol + 2] = to_tf32(v.z);
            Bs[r][bcol + 3] = to_tf32(v.w);
        }
        __syncthreads();

#pragma unroll
        for (int kk = 0; kk < 32; kk += 8) {
            uint32_t a[4][4], b[4][2];
            const int g = lane >> 2;
            const int l = lane & 3;
#pragma unroll
            for (int mi = 0; mi < 4; mi++) {
                int r = wm + mi * 16 + g;
                a[mi][0] = __float_as_uint(As[r][kk + l]);
                a[mi][1] = __float_as_uint(As[r + 8][kk + l]);
                a[mi][2] = __float_as_uint(As[r][kk + l + 4]);
                a[mi][3] = __float_as_uint(As[r + 8][kk + l + 4]);
            }
#pragma unroll
            for (int ni = 0; ni < 4; ni++) {
                int ncol = wn + ni * 8 + g;
                b[ni][0] = __float_as_uint(Bs[kk + l][ncol]);
                b[ni][1] = __float_as_uint(Bs[kk + l + 4][ncol]);
            }
#pragma unroll
            for (int mi = 0; mi < 4; mi++)
#pragma unroll
                for (int ni = 0; ni < 4; ni++) {
                    asm volatile(
                        "mma.sync.aligned.m16n8k8.row.col.f32.tf32.tf32.f32 "
                        "{%0,%1,%2,%3}, {%4,%5,%6,%7}, {%8,%9}, {%0,%1,%2,%3};\n"
                        : "+f"(c[mi][ni][0]), "+f"(c[mi][ni][1]),
                          "+f"(c[mi][ni][2]), "+f"(c[mi][ni][3])
                        : "r"(a[mi][0]), "r"(a[mi][1]), "r"(a[mi][2]), "r"(a[mi][3]),
                          "r"(b[ni][0]), "r"(b[ni][1]));
                }
        }
        __syncthreads();
    }

    const int g = lane >> 2;
    const int l = lane & 3;
    const int hh = nBase / HID;   // head owned by this block column

#pragma unroll
    for (int mi = 0; mi < 4; mi++) {
        int r0 = mBase + wm + mi * 16 + g;
        int r1 = r0 + 8;
        float ps0 = 0.f, pd0 = 0.f, ps1 = 0.f, pd1 = 0.f;
#pragma unroll
        for (int ni = 0; ni < 4; ni++) {
            int col = nBase + wn + ni * 8 + 2 * l;
            if (r0 < M)
                *(__half2*)&C[(size_t)r0 * N + col] =
                    __float22half2_rn(make_float2(c[mi][ni][0], c[mi][ni][1]));
            if (r1 < M)
                *(__half2*)&C[(size_t)r1 * N + col] =
                    __float22half2_rn(make_float2(c[mi][ni][2], c[mi][ni][3]));
            int cc = wn + ni * 8 + 2 * l;  // within-head channel
            float sa0 = a_src[hh * HID + cc],     sa1 = a_src[hh * HID + cc + 1];
            float da0 = a_dst[hh * HID + cc],     da1 = a_dst[hh * HID + cc + 1];
            ps0 += c[mi][ni][0] * sa0 + c[mi][ni][1] * sa1;
            pd0 += c[mi][ni][0] * da0 + c[mi][ni][1] * da1;
            ps1 += c[mi][ni][2] * sa0 + c[mi][ni][3] * sa1;
            pd1 += c[mi][ni][2] * da0 + c[mi][ni][3] * da1;
        }
#pragma unroll
        for (int o = 1; o <= 2; o <<= 1) {
            ps0 += __shfl_xor_sync(0xffffffffu, ps0, o);
            pd0 += __shfl_xor_sync(0xffffffffu, pd0, o);
            ps1 += __shfl_xor_sync(0xffffffffu, ps1, o);
            pd1 += __shfl_xor_sync(0xffffffffu, pd1, o);
        }
        if (l == 0) {
            if (r0 < M) {
                atomicAdd(&as_out[r0 * H + hh], ps0);
                atomicAdd(&ad_out[r0 * H + hh], pd0);
            }
            if (r1 < M) {
                atomicAdd(&as_out[r1 * H + hh], ps1);
                atomicAdd(&ad_out[r1 * H + hh], pd1);
            }
        }
    }
}

// ==================== CSR build ====================
__global__ void deg_kernel(const int* __restrict__ dst, int* __restrict__ deg, int E)
{
    int e = blockIdx.x * blockDim.x + threadIdx.x;
    if (e < E) atomicAdd(&deg[dst[e]], 1);
}

__global__ __launch_bounds__(1024) void scan_kernel(const int* __restrict__ deg,
                                                    int* __restrict__ rowstart, int n)
{
    __shared__ int warp_sums[32];
    __shared__ int s_carry;
    int t = threadIdx.x;
    int lane = t & 31, w = t >> 5;
    if (t == 0) s_carry = 0;
    __syncthreads();
    for (int base = 0; base < n; base += 1024) {
        int i = base + t;
        int x = (i < n) ? deg[i] : 0;
        int v = x;
#pragma unroll
        for (int o = 1; o < 32; o <<= 1) {
            int y = __shfl_up_sync(0xffffffffu, v, o);
            if (lane >= o) v += y;
        }
        if (lane == 31) warp_sums[w] = v;
        __syncthreads();
        if (w == 0) {
            int s = warp_sums[lane];
#pragma unroll
            for (int o = 1; o < 32; o <<= 1) {
                int y = __shfl_up_sync(0xffffffffu, s, o);
                if (lane >= o) s += y;
            }
            warp_sums[lane] = s;
        }
        __syncthreads();
        int prefix = s_carry + (w > 0 ? warp_sums[w - 1] : 0) + v - x;
        if (i < n) rowstart[i] = prefix;
        __syncthreads();
        if (t == 0) s_carry += warp_sums[31];
        __syncthreads();
    }
    if (t == 0) rowstart[n] = s_carry;
}

__global__ void csr_scatter_kernel(const int* __restrict__ src, const int* __restrict__ dst,
                                   int* __restrict__ cursor, int* __restrict__ csr_src, int E)
{
    int e = blockIdx.x * blockDim.x + threadIdx.x;
    if (e >= E) return;
    int p = atomicAdd(&cursor[dst[e]], 1);
    csr_src[p] = src[e];
}

// ==================== edge coefficient kernel (warp per node) ====================
template <int H>
__global__ __launch_bounds__(128) void coef_kernel(
    const int* __restrict__ rowstart, const int* __restrict__ csr_src,
    const float* __restrict__ as_, const float* __restrict__ ad_,
    float* __restrict__ coef, int n)
{
    const int d = blockIdx.x * 4 + (threadIdx.x >> 5);
    const int lane = threadIdx.x & 31;
    if (d >= n) return;
    const int e0 = rowstart[d];
    const int deg = rowstart[d + 1] - e0;

    float adv[H];
#pragma unroll
    for (int h = 0; h < H; h++) adv[h] = ad_[d * H + h];

    float mx[H];
#pragma unroll
    for (int h = 0; h < H; h++) mx[h] = -__int_as_float(0x7f800000);
    for (int j = lane; j < deg; j += 32) {
        int s = __ldg(&csr_src[e0 + j]);
        if (H == 4) {
            float4 av = __ldg((const float4*)&as_[s * 4]);
            float v0 = av.x + adv[0]; v0 = (v0 >= 0.f) ? v0 : NEG_SLOPE * v0;
            float v1 = av.y + adv[1]; v1 = (v1 >= 0.f) ? v1 : NEG_SLOPE * v1;
            float v2 = av.z + adv[2]; v2 = (v2 >= 0.f) ? v2 : NEG_SLOPE * v2;
            float v3 = av.w + adv[3]; v3 = (v3 >= 0.f) ? v3 : NEG_SLOPE * v3;
            mx[0] = fmaxf(mx[0], v0); mx[1] = fmaxf(mx[1], v1);
            mx[2] = fmaxf(mx[2], v2); mx[3] = fmaxf(mx[3], v3);
        } else {
            float v = __ldg(&as_[s]) + adv[0];
            v = (v >= 0.f) ? v : NEG_SLOPE * v;
            mx[0] = fmaxf(mx[0], v);
        }
    }
#pragma unroll
    for (int h = 0; h < H; h++)
#pragma unroll
        for (int o = 16; o; o >>= 1)
            mx[h] = fmaxf(mx[h], __shfl_xor_sync(0xffffffffu, mx[h], o));

    float sm[H];
#pragma unroll
    for (int h = 0; h < H; h++) sm[h] = 0.f;
    for (int j = lane; j < deg; j += 32) {
        int s = __ldg(&csr_src[e0 + j]);
        if (H == 4) {
            float4 av = __ldg((const float4*)&as_[s * 4]);
            float v0 = av.x + adv[0]; v0 = (v0 >= 0.f) ? v0 : NEG_SLOPE * v0;
            float v1 = av.y + adv[1]; v1 = (v1 >= 0.f) ? v1 : NEG_SLOPE * v1;
            float v2 = av.z + adv[2]; v2 = (v2 >= 0.f) ? v2 : NEG_SLOPE * v2;
            float v3 = av.w + adv[3]; v3 = (v3 >= 0.f) ? v3 : NEG_SLOPE * v3;
            sm[0] += expf(v0 - mx[0]); sm[1] += expf(v1 - mx[1]);
            sm[2] += expf(v2 - mx[2]); sm[3] += expf(v3 - mx[3]);
        } else {
            float v = __ldg(&as_[s]) + adv[0];
            v = (v >= 0.f) ? v : NEG_SLOPE * v;
            sm[0] += expf(v - mx[0]);
        }
    }
#pragma unroll
    for (int h = 0; h < H; h++)
#pragma unroll
        for (int o = 16; o; o >>= 1)
            sm[h] += __shfl_xor_sync(0xffffffffu, sm[h], o);

    float inv[H];
#pragma unroll
    for (int h = 0; h < H; h++) inv[h] = 1.f / (sm[h] + 1e-16f);

    for (int j = lane; j < deg; j += 32) {
        int s = __ldg(&csr_src[e0 + j]);
        if (H == 4) {
            float4 av = __ldg((const float4*)&as_[s * 4]);
            float v0 = av.x + adv[0]; v0 = (v0 >= 0.f) ? v0 : NEG_SLOPE * v0;
            float v1 = av.y + adv[1]; v1 = (v1 >= 0.f) ? v1 : NEG_SLOPE * v1;
            float v2 = av.z + adv[2]; v2 = (v2 >= 0.f) ? v2 : NEG_SLOPE * v2;
            float v3 = av.w + adv[3]; v3 = (v3 >= 0.f) ? v3 : NEG_SLOPE * v3;
            float4 cf;
            cf.x = expf(v0 - mx[0]) * inv[0];
            cf.y = expf(v1 - mx[1]) * inv[1];
            cf.z = expf(v2 - mx[2]) * inv[2];
            cf.w = expf(v3 - mx[3]) * inv[3];
            *(float4*)&coef[(size_t)(e0 + j) * 4] = cf;
        } else {
            float v = __ldg(&as_[s]) + adv[0];
            v = (v >= 0.f) ? v : NEG_SLOPE * v;
            coef[e0 + j] = expf(v - mx[0]) * inv[0];
        }
    }
}

// ==================== SpMM aggregate + bias + ELU (block per node, fp16 gather) ====================
template <int H>
__global__ __launch_bounds__(128) void spmm_kernel(
    const int* __restrict__ rowstart, const int* __restrict__ csr_src,
    const float* __restrict__ coef, const __half* __restrict__ hbuf,
    const float* __restrict__ bias, float* __restrict__ out, int do_elu)
{
    const int d = blockIdx.x;
    const int t = threadIdx.x;
    const int e0 = rowstart[d];
    const int deg = rowstart[d + 1] - e0;
    const int W = H * HID;
    const int c0 = t * H;               // this thread's channel base
    const int hd = (H == 4) ? (t >> 5) : 0;

    float acc0 = 0.f, acc1 = 0.f, acc2 = 0.f, acc3 = 0.f;

#pragma unroll 4
    for (int j = 0; j < deg; j++) {
        int s = __ldg(&csr_src[e0 + j]);                          // broadcast
        float cf = __ldg(&coef[(size_t)(e0 + j) * H + hd]);       // broadcast/warp
        if (H == 4) {
            // 4 fp16 = 8 bytes, aligned (c0*2 = t*8)
            uint2 raw = __ldg((const uint2*)(hbuf + (size_t)s * W + c0));
            float2 p0 = __half22float2(*(__half2*)&raw.x);
            float2 p1 = __half22float2(*(__half2*)&raw.y);
            acc0 += p0.x * cf; acc1 += p0.y * cf;
            acc2 += p1.x * cf; acc3 += p1.y * cf;
        } else {
            acc0 += __half2float(__ldg(hbuf + (size_t)s * W + c0)) * cf;
        }
    }

    if (H == 4) {
        float4 b = *(const float4*)&bias[c0];
        float v0 = acc0 + b.x, v1 = acc1 + b.y, v2 = acc2 + b.z, v3 = acc3 + b.w;
        if (do_elu) {
            v0 = (v0 > 0.f) ? v0 : expm1f(v0);
            v1 = (v1 > 0.f) ? v1 : expm1f(v1);
            v2 = (v2 > 0.f) ? v2 : expm1f(v2);
            v3 = (v3 > 0.f) ? v3 : expm1f(v3);
        }
        *(float4*)&out[(size_t)d * W + c0] = make_float4(v0, v1, v2, v3);
    } else {
        float v = acc0 + bias[c0];
        if (do_elu) v = (v > 0.f) ? v : expm1f(v);
        out[(size_t)d * W + c0] = v;
    }
}

// ==================== pooling ====================
__global__ void pool_sum_kernel(const float* __restrict__ node_emb, const int* __restrict__ batch,
                                float* __restrict__ pool, float* __restrict__ cnt, int n)
{
    int node = blockIdx.x;
    int t = threadIdx.x;
    int g = batch[node];
    atomicAdd(&pool[g * HID + t], node_emb[(size_t)node * HID + t]);
    if (t == 0) atomicAdd(&cnt[g], 1.0f);
}

__global__ void pool_div_kernel(const float* __restrict__ pool, const float* __restrict__ cnt,
                                float* __restrict__ out)
{
    int i = blockIdx.x * blockDim.x + threadIdx.x;
    if (i >= NGRAPH * HID) return;
    int g = i / HID;
    out[i] = pool[i] / fmaxf(cnt[g], 1.0f);
}

// ==================== host side ====================
static void run_gat_layer(const float* in, int fin,
                          const float* W, const float* a_s, const float* a_d, const float* bias,
                          int heads, float* out, int do_elu,
                          int n, const int* rowstart, const int* csr_src,
                          __half* hbuf, float* asb, float* adb, float* coefb)
{
    const int width = heads * HID;

    cudaMemsetAsync(asb, 0, (size_t)n * heads * sizeof(float));
    cudaMemsetAsync(adb, 0, (size_t)n * heads * sizeof(float));

    dim3 ggrid(width / 128, (n + 127) / 128);
    tf32_gemm_alpha_kernel<<<ggrid, 256>>>(in, W, hbuf, n, fin, width,
                                           a_s, a_d, asb, adb, heads);

    int cgrid = (n + 3) / 4;
    if (heads == 4) {
        coef_kernel<4><<<cgrid, 128>>>(rowstart, csr_src, asb, adb, coefb, n);
        spmm_kernel<4><<<n, 128>>>(rowstart, csr_src, coefb, hbuf, bias, out, do_elu);
    } else {
        coef_kernel<1><<<cgrid, 128>>>(rowstart, csr_src, asb, adb, coefb, n);
        spmm_kernel<1><<<n, 128>>>(rowstart, csr_src, coefb, hbuf, bias, out, do_elu);
    }
}

extern "C" void kernel_launch(void* const* d_in, const int* in_sizes, int n_in,
                              void* d_out, int out_size)
{
    const float* x     = (const float*)d_in[0];
    const int*   ei    = (const int*)d_in[1];
    const int*   batch = (const int*)d_in[2];
    const float* W1  = (const float*)d_in[3];
    const float* a1s = (const float*)d_in[4];
    const float* a1d = (const float*)d_in[5];
    const float* b1  = (const float*)d_in[6];
    const float* W2  = (const float*)d_in[7];
    const float* a2s = (const float*)d_in[8];
    const float* a2d = (const float*)d_in[9];
    const float* b2  = (const float*)d_in[10];
    const float* W3  = (const float*)d_in[11];
    const float* a3s = (const float*)d_in[12];
    const float* a3d = (const float*)d_in[13];
    const float* b3  = (const float*)d_in[14];

    const int n = in_sizes[0] / FIN;
    const int E = in_sizes[1] / 2;
    const int* src = ei;
    const int* dst = ei + E;

    float *actbuf, *asb, *adb, *coefb, *poolb, *cntb;
    __half* hbuf;
    int *degb, *rowstartb, *cursorb, *csrsrcb;
    cudaGetSymbolAddress((void**)&hbuf,      g_hh);
    cudaGetSymbolAddress((void**)&actbuf,    g_act);
    cudaGetSymbolAddress((void**)&asb,       g_as);
    cudaGetSymbolAddress((void**)&adb,       g_ad);
    cudaGetSymbolAddress((void**)&degb,      g_deg);
    cudaGetSymbolAddress((void**)&rowstartb, g_rowstart);
    cudaGetSymbolAddress((void**)&cursorb,   g_cursor);
    cudaGetSymbolAddress((void**)&csrsrcb,   g_csr_src);
    cudaGetSymbolAddress((void**)&coefb,     g_coef);
    cudaGetSymbolAddress((void**)&poolb,     g_pool);
    cudaGetSymbolAddress((void**)&cntb,      g_cnt);

    float* node_emb  = (float*)d_out;
    float* graph_emb = (float*)d_out + (size_t)n * HID;

    // ---- CSR build (once, shared by all 3 layers) ----
    cudaMemsetAsync(degb, 0, (size_t)n * sizeof(int));
    deg_kernel<<<(E + 255) / 256, 256>>>(dst, degb, E);
    scan_kernel<<<1, 1024>>>(degb, rowstartb, n);
    cudaMemcpyAsync(cursorb, rowstartb, (size_t)n * sizeof(int), cudaMemcpyDeviceToDevice);
    csr_scatter_kernel<<<(E + 255) / 256, 256>>>(src, dst, cursorb, csrsrcb, E);

    // ---- layers ----
    run_gat_layer(x, FIN, W1, a1s, a1d, b1, HEADS, actbuf, 1,
                  n, rowstartb, csrsrcb, hbuf, asb, adb, coefb);
    run_gat_layer(actbuf, HEADS * HID, W2, a2s, a2d, b2, HEADS, actbuf, 1,
                  n, rowstartb, csrsrcb, hbuf, asb, adb, coefb);
    run_gat_layer(actbuf, HEADS * HID, W3, a3s, a3d, b3, 1, node_emb, 0,
                  n, rowstartb, csrsrcb, hbuf, asb, adb, coefb);

    // ---- global mean pool ----
    cudaMemsetAsync(poolb, 0, NGRAPH * HID * sizeof(float));
    cudaMemsetAsync(cntb, 0, NGRAPH * sizeof(float));
    pool_sum_kernel<<<n, HID>>>(node_emb, batch, poolb, cntb, n);
    pool_div_kernel<<<(NGRAPH * HID + 127) / 128, 128>>>(poolb, cntb, graph_emb);
}

// round 7
// speedup vs baseline: 1.1385x; 1.1385x over previous
#include <cuda_runtime.h>
#include <cuda_fp16.h>
#include <cstdint>
#include <cstddef>

#define NN 50000
#define EE 800000
#define FIN 256
#define HID 128
#define HEADS 4
#define NGRAPH 50
#define NEG_SLOPE 0.2f

// ---------------- scratch (device globals; no allocation allowed) -------------
__device__ __half g_hh[(size_t)NN * HEADS * HID];   // GEMM output (fp16 messages)
__device__ float g_act[(size_t)NN * HEADS * HID];   // aggregated output / next input
__device__ float g_alpha[2 * NN * HEADS];           // [0]=as, [NN*HEADS]=ad
__device__ int   g_deg[NN];
__device__ int   g_rowstart[NN + 1];
__device__ int   g_cursor[NN];
__device__ int   g_csr_src[EE];
__device__ float g_coef[(size_t)EE * HEADS];        // normalized alpha, CSR order
__device__ float g_pool[NGRAPH * HID];
__device__ float g_cnt[NGRAPH];

// ==================== TF32 tensor-core GEMM + fused alpha epilogue ====================
__device__ __forceinline__ float to_tf32(float x) {
    float y;
    asm("cvt.rna.tf32.f32 %0, %1;" : "=f"(y) : "f"(x));
    return y;
}

__global__ __launch_bounds__(256) void tf32_gemm_alpha_kernel(
    const float* __restrict__ A, const float* __restrict__ B, __half* __restrict__ C,
    int M, int K, int N,
    const float* __restrict__ a_src, const float* __restrict__ a_dst,  // [H][HID]
    float* __restrict__ as_out, float* __restrict__ ad_out, int H)
{
    __shared__ __align__(16) float As[128][36];
    __shared__ __align__(16) float Bs[32][136];

    const int tid  = threadIdx.x;
    const int lane = tid & 31;
    const int warp = tid >> 5;
    const int wm = (warp & 1) * 64;
    const int wn = (warp >> 1) * 32;

    const int mBase = blockIdx.y * 128;
    const int nBase = blockIdx.x * 128;

    float c[4][4][4];
#pragma unroll
    for (int mi = 0; mi < 4; mi++)
#pragma unroll
        for (int ni = 0; ni < 4; ni++)
#pragma unroll
            for (int q = 0; q < 4; q++) c[mi][ni][q] = 0.f;

    const int arow = tid >> 3;
    const int acol = (tid & 7) * 4;
    const int brow = tid >> 5;
    const int bcol = (tid & 31) * 4;

    for (int k0 = 0; k0 < K; k0 += 32) {
#pragma unroll
        for (int p = 0; p < 4; p++) {
            int r = arow + p * 32;
            int gr = mBase + r;
            float4 v = make_float4(0.f, 0.f, 0.f, 0.f);
            if (gr < M) v = *(const float4*)&A[(size_t)gr * K + k0 + acol];
            As[r][acol + 0] = to_tf32(v.x);
            As[r][acol + 1] = to_tf32(v.y);
            As[r][acol + 2] = to_tf32(v.z);
            As[r][acol + 3] = to_tf32(v.w);
        }
#pragma unroll
        for (int p = 0; p < 4; p++) {
            int r = brow + p * 8;
            float4 v = *(const float4*)&B[(size_t)(k0 + r) * N + nBase + bcol];
            Bs[r][bcol + 0] = to_tf32(v.x);
            Bs[r][bcol + 1] = to_tf32(v.y);
            Bs[r][bcol + 2] = to_tf32(v.z);
            Bs[r][bcol + 3] = to_tf32(v.w);
        }
        __syncthreads();

#pragma unroll
        for (int kk = 0; kk < 32; kk += 8) {
            uint32_t a[4][4], b[4][2];
            const int g = lane >> 2;
            const int l = lane & 3;
#pragma unroll
            for (int mi = 0; mi < 4; mi++) {
                int r = wm + mi * 16 + g;
                a[mi][0] = __float_as_uint(As[r][kk + l]);
                a[mi][1] = __float_as_uint(As[r + 8][kk + l]);
                a[mi][2] = __float_as_uint(As[r][kk + l + 4]);
                a[mi][3] = __float_as_uint(As[r + 8][kk + l + 4]);
            }
#pragma unroll
            for (int ni = 0; ni < 4; ni++) {
                int ncol = wn + ni * 8 + g;
                b[ni][0] = __float_as_uint(Bs[kk + l][ncol]);
                b[ni][1] = __float_as_uint(Bs[kk + l + 4][ncol]);
            }
#pragma unroll
            for (int mi = 0; mi < 4; mi++)
#pragma unroll
                for (int ni = 0; ni < 4; ni++) {
                    asm volatile(
                        "mma.sync.aligned.m16n8k8.row.col.f32.tf32.tf32.f32 "
                        "{%0,%1,%2,%3}, {%4,%5,%6,%7}, {%8,%9}, {%0,%1,%2,%3};\n"
                        : "+f"(c[mi][ni][0]), "+f"(c[mi][ni][1]),
                          "+f"(c[mi][ni][2]), "+f"(c[mi][ni][3])
                        : "r"(a[mi][0]), "r"(a[mi][1]), "r"(a[mi][2]), "r"(a[mi][3]),
                          "r"(b[ni][0]), "r"(b[ni][1]));
                }
        }
        __syncthreads();
    }

    const int g = lane >> 2;
    const int l = lane & 3;
    const int hh = nBase / HID;

#pragma unroll
    for (int mi = 0; mi < 4; mi++) {
        int r0 = mBase + wm + mi * 16 + g;
        int r1 = r0 + 8;
        float ps0 = 0.f, pd0 = 0.f, ps1 = 0.f, pd1 = 0.f;
#pragma unroll
        for (int ni = 0; ni < 4; ni++) {
            int col = nBase + wn + ni * 8 + 2 * l;
            if (r0 < M)
                *(__half2*)&C[(size_t)r0 * N + col] =
                    __float22half2_rn(make_float2(c[mi][ni][0], c[mi][ni][1]));
            if (r1 < M)
                *(__half2*)&C[(size_t)r1 * N + col] =
                    __float22half2_rn(make_float2(c[mi][ni][2], c[mi][ni][3]));
            int cc = wn + ni * 8 + 2 * l;
            float sa0 = a_src[hh * HID + cc],     sa1 = a_src[hh * HID + cc + 1];
            float da0 = a_dst[hh * HID + cc],     da1 = a_dst[hh * HID + cc + 1];
            ps0 += c[mi][ni][0] * sa0 + c[mi][ni][1] * sa1;
            pd0 += c[mi][ni][0] * da0 + c[mi][ni][1] * da1;
            ps1 += c[mi][ni][2] * sa0 + c[mi][ni][3] * sa1;
            pd1 += c[mi][ni][2] * da0 + c[mi][ni][3] * da1;
        }
#pragma unroll
        for (int o = 1; o <= 2; o <<= 1) {
            ps0 += __shfl_xor_sync(0xffffffffu, ps0, o);
            pd0 += __shfl_xor_sync(0xffffffffu, pd0, o);
            ps1 += __shfl_xor_sync(0xffffffffu, ps1, o);
            pd1 += __shfl_xor_sync(0xffffffffu, pd1, o);
        }
        if (l == 0) {
            if (r0 < M) {
                atomicAdd(&as_out[r0 * H + hh], ps0);
                atomicAdd(&ad_out[r0 * H + hh], pd0);
            }
            if (r1 < M) {
                atomicAdd(&as_out[r1 * H + hh], ps1);
                atomicAdd(&ad_out[r1 * H + hh], pd1);
            }
        }
    }
}

// ==================== CSR build ====================
__global__ void deg_kernel(const int* __restrict__ dst, int* __restrict__ deg, int E)
{
    int e = blockIdx.x * blockDim.x + threadIdx.x;
    if (e < E) atomicAdd(&deg[dst[e]], 1);
}

__global__ __launch_bounds__(1024) void scan_kernel(const int* __restrict__ deg,
                                                    int* __restrict__ rowstart, int n)
{
    __shared__ int warp_sums[32];
    __shared__ int s_carry;
    int t = threadIdx.x;
    int lane = t & 31, w = t >> 5;
    if (t == 0) s_carry = 0;
    __syncthreads();
    for (int base = 0; base < n; base += 1024) {
        int i = base + t;
        int x = (i < n) ? deg[i] : 0;
        int v = x;
#pragma unroll
        for (int o = 1; o < 32; o <<= 1) {
            int y = __shfl_up_sync(0xffffffffu, v, o);
            if (lane >= o) v += y;
        }
        if (lane == 31) warp_sums[w] = v;
        __syncthreads();
        if (w == 0) {
            int s = warp_sums[lane];
#pragma unroll
            for (int o = 1; o < 32; o <<= 1) {
                int y = __shfl_up_sync(0xffffffffu, s, o);
                if (lane >= o) s += y;
            }
            warp_sums[lane] = s;
        }
        __syncthreads();
        int prefix = s_carry + (w > 0 ? warp_sums[w - 1] : 0) + v - x;
        if (i < n) rowstart[i] = prefix;
        __syncthreads();
        if (t == 0) s_carry += warp_sums[31];
        __syncthreads();
    }
    if (t == 0) rowstart[n] = s_carry;
}

__global__ void csr_scatter_kernel(const int* __restrict__ src, const int* __restrict__ dst,
                                   int* __restrict__ cursor, int* __restrict__ csr_src, int E)
{
    int e = blockIdx.x * blockDim.x + threadIdx.x;
    if (e >= E) return;
    int p = atomicAdd(&cursor[dst[e]], 1);
    csr_src[p] = src[e];
}

// ==================== edge coefficient kernel (warp per node, 1-pass fast path) ====================
template <int H>
__global__ __launch_bounds__(256) void coef_kernel(
    const int* __restrict__ rowstart, const int* __restrict__ csr_src,
    const float* __restrict__ as_, const float* __restrict__ ad_,
    float* __restrict__ coef, int n)
{
    const int d = blockIdx.x * 8 + (threadIdx.x >> 5);
    const int lane = threadIdx.x & 31;
    if (d >= n) return;
    const int e0 = rowstart[d];
    const int deg = rowstart[d + 1] - e0;
    const float NEG_INF = -__int_as_float(0x7f800000);

    float adv[H];
#pragma unroll
    for (int h = 0; h < H; h++) adv[h] = ad_[d * H + h];

    if (deg <= 32) {
        // ---- fast path: one edge per lane, single gather ----
        bool valid = lane < deg;
        float v[H];
        if (valid) {
            int s = __ldg(&csr_src[e0 + lane]);
            if (H == 4) {
                float4 av = __ldg((const float4*)&as_[s * 4]);
                v[0] = av.x + adv[0]; v[1] = av.y + adv[1];
                v[2] = av.z + adv[2]; v[3] = av.w + adv[3];
            } else {
                v[0] = __ldg(&as_[s]) + adv[0];
            }
#pragma unroll
            for (int h = 0; h < H; h++) v[h] = (v[h] >= 0.f) ? v[h] : NEG_SLOPE * v[h];
        } else {
#pragma unroll
            for (int h = 0; h < H; h++) v[h] = NEG_INF;
        }
        float mx[H], sm[H];
#pragma unroll
        for (int h = 0; h < H; h++) {
            mx[h] = v[h];
#pragma unroll
            for (int o = 16; o; o >>= 1)
                mx[h] = fmaxf(mx[h], __shfl_xor_sync(0xffffffffu, mx[h], o));
            float e = valid ? expf(v[h] - mx[h]) : 0.f;
            sm[h] = e;
#pragma unroll
            for (int o = 16; o; o >>= 1)
                sm[h] += __shfl_xor_sync(0xffffffffu, sm[h], o);
            v[h] = e / (sm[h] + 1e-16f);   // reuse v as coefficient
        }
        if (valid) {
            if (H == 4)
                *(float4*)&coef[(size_t)(e0 + lane) * 4] = make_float4(v[0], v[1], v[2], v[3]);
            else
                coef[e0 + lane] = v[0];
        }
        return;
    }

    // ---- generic 3-pass path (deg > 32, rare) ----
    float mx[H];
#pragma unroll
    for (int h = 0; h < H; h++) mx[h] = NEG_INF;
    for (int j = lane; j < deg; j += 32) {
        int s = __ldg(&csr_src[e0 + j]);
#pragma unroll
        for (int h = 0; h < H; h++) {
            float v = as_[s * H + h] + adv[h];
            v = (v >= 0.f) ? v : NEG_SLOPE * v;
            mx[h] = fmaxf(mx[h], v);
        }
    }
#pragma unroll
    for (int h = 0; h < H; h++)
#pragma unroll
        for (int o = 16; o; o >>= 1)
            mx[h] = fmaxf(mx[h], __shfl_xor_sync(0xffffffffu, mx[h], o));

    float sm[H];
#pragma unroll
    for (int h = 0; h < H; h++) sm[h] = 0.f;
    for (int j = lane; j < deg; j += 32) {
        int s = __ldg(&csr_src[e0 + j]);
#pragma unroll
        for (int h = 0; h < H; h++) {
            float v = as_[s * H + h] + adv[h];
            v = (v >= 0.f) ? v : NEG_SLOPE * v;
            sm[h] += expf(v - mx[h]);
        }
    }
#pragma unroll
    for (int h = 0; h < H; h++) {
#pragma unroll
        for (int o = 16; o; o >>= 1)
            sm[h] += __shfl_xor_sync(0xffffffffu, sm[h], o);
        sm[h] = 1.f / (sm[h] + 1e-16f);
    }
    for (int j = lane; j < deg; j += 32) {
        int s = __ldg(&csr_src[e0 + j]);
#pragma unroll
        for (int h = 0; h < H; h++) {
            float v = as_[s * H + h] + adv[h];
            v = (v >= 0.f) ? v : NEG_SLOPE * v;
            coef[(size_t)(e0 + j) * H + h] = expf(v - mx[h]) * sm[h];
        }
    }
}

// ==================== SpMM aggregate + bias + ELU (warp per node) ====================
// H=4: lane owns 16 fp16 channels (32B, two LDG.128 per edge).
// H=1: lane owns 4 fp16 channels (8B, one LDG.64 per edge).
template <int H>
__global__ __launch_bounds__(256) void spmm_kernel(
    const int* __restrict__ rowstart, const int* __restrict__ csr_src,
    const float* __restrict__ coef, const __half* __restrict__ hbuf,
    const float* __restrict__ bias, float* __restrict__ out, int do_elu)
{
    const int d = blockIdx.x * 8 + (threadIdx.x >> 5);
    const int lane = threadIdx.x & 31;
    if (d >= gridDim.y) {} // unused
    const int e0 = rowstart[d];
    const int deg = rowstart[d + 1] - e0;
    const int W = H * HID;
    const int CH = (H == 4) ? 16 : 4;          // fp16 channels per lane
    const int c0 = lane * CH;

    float acc[16];
#pragma unroll
    for (int i = 0; i < CH; i++) acc[i] = 0.f;

#pragma unroll 4
    for (int j = 0; j < deg; j++) {
        int s = __ldg(&csr_src[e0 + j]);
        const __half* hp = hbuf + (size_t)s * W + c0;
        if (H == 4) {
            float cf = __ldg(&coef[(size_t)(e0 + j) * 4 + (lane >> 3)]);
            uint4 r0 = __ldg((const uint4*)hp);
            uint4 r1 = __ldg((const uint4*)(hp + 8));
            const __half2* p0 = (const __half2*)&r0;
            const __half2* p1 = (const __half2*)&r1;
#pragma unroll
            for (int q = 0; q < 4; q++) {
                float2 f0 = __half22float2(p0[q]);
                float2 f1 = __half22float2(p1[q]);
                acc[2 * q + 0] += f0.x * cf;
                acc[2 * q + 1] += f0.y * cf;
                acc[8 + 2 * q + 0] += f1.x * cf;
                acc[8 + 2 * q + 1] += f1.y * cf;
            }
        } else {
            float cf = __ldg(&coef[e0 + j]);
            uint2 r0 = __ldg((const uint2*)hp);
            const __half2* p0 = (const __half2*)&r0;
#pragma unroll
            for (int q = 0; q < 2; q++) {
                float2 f0 = __half22float2(p0[q]);
                acc[2 * q + 0] += f0.x * cf;
                acc[2 * q + 1] += f0.y * cf;
            }
        }
    }

    // epilogue
#pragma unroll
    for (int i = 0; i < CH; i += 4) {
        float4 b = *(const float4*)&bias[c0 + i];
        float v0 = acc[i + 0] + b.x, v1 = acc[i + 1] + b.y;
        float v2 = acc[i + 2] + b.z, v3 = acc[i + 3] + b.w;
        if (do_elu) {
            v0 = (v0 > 0.f) ? v0 : expm1f(v0);
            v1 = (v1 > 0.f) ? v1 : expm1f(v1);
            v2 = (v2 > 0.f) ? v2 : expm1f(v2);
            v3 = (v3 > 0.f) ? v3 : expm1f(v3);
        }
        *(float4*)&out[(size_t)d * W + c0 + i] = make_float4(v0, v1, v2, v3);
    }
}

// ==================== pooling ====================
__global__ void pool_sum_kernel(const float* __restrict__ node_emb, const int* __restrict__ batch,
                                float* __restrict__ pool, float* __restrict__ cnt, int n)
{
    int node = blockIdx.x;
    int t = threadIdx.x;
    int g = batch[node];
    atomicAdd(&pool[g * HID + t], node_emb[(size_t)node * HID + t]);
    if (t == 0) atomicAdd(&cnt[g], 1.0f);
}

__global__ void pool_div_kernel(const float* __restrict__ pool, const float* __restrict__ cnt,
                                float* __restrict__ out)
{
    int i = blockIdx.x * blockDim.x + threadIdx.x;
    if (i >= NGRAPH * HID) return;
    int g = i / HID;
    out[i] = pool[i] / fmaxf(cnt[g], 1.0f);
}

// ==================== host side ====================
static void run_gat_layer(const float* in, int fin,
                          const float* W, const float* a_s, const float* a_d, const float* bias,
                          int heads, float* out, int do_elu,
                          int n, const int* rowstart, const int* csr_src,
                          __half* hbuf, float* alphab, float* coefb)
{
    const int width = heads * HID;
    float* asb = alphab;
    float* adb = alphab + NN * HEADS;

    cudaMemsetAsync(alphab, 0, (size_t)2 * NN * HEADS * sizeof(float));

    dim3 ggrid(width / 128, (n + 127) / 128);
    tf32_gemm_alpha_kernel<<<ggrid, 256>>>(in, W, hbuf, n, fin, width,
                                           a_s, a_d, asb, adb, heads);

    int wgrid = (n + 7) / 8;
    if (heads == 4) {
        coef_kernel<4><<<wgrid, 256>>>(rowstart, csr_src, asb, adb, coefb, n);
        spmm_kernel<4><<<wgrid * 8 / 8, 256>>>(rowstart, csr_src, coefb, hbuf, bias, out, do_elu);
    } else {
        coef_kernel<1><<<wgrid, 256>>>(rowstart, csr_src, asb, adb, coefb, n);
        spmm_kernel<1><<<wgrid, 256>>>(rowstart, csr_src, coefb, hbuf, bias, out, do_elu);
    }
}

extern "C" void kernel_launch(void* const* d_in, const int* in_sizes, int n_in,
                              void* d_out, int out_size)
{
    const float* x     = (const float*)d_in[0];
    const int*   ei    = (const int*)d_in[1];
    const int*   batch = (const int*)d_in[2];
    const float* W1  = (const float*)d_in[3];
    const float* a1s = (const float*)d_in[4];
    const float* a1d = (const float*)d_in[5];
    const float* b1  = (const float*)d_in[6];
    const float* W2  = (const float*)d_in[7];
    const float* a2s = (const float*)d_in[8];
    const float* a2d = (const float*)d_in[9];
    const float* b2  = (const float*)d_in[10];
    const float* W3  = (const float*)d_in[11];
    const float* a3s = (const float*)d_in[12];
    const float* a3d = (const float*)d_in[13];
    const float* b3  = (const float*)d_in[14];

    const int n = in_sizes[0] / FIN;
    const int E = in_sizes[1] / 2;
    const int* src = ei;
    const int* dst = ei + E;

    float *actbuf, *alphab, *coefb, *poolb, *cntb;
    __half* hbuf;
    int *degb, *rowstartb, *cursorb, *csrsrcb;
    cudaGetSymbolAddress((void**)&hbuf,      g_hh);
    cudaGetSymbolAddress((void**)&actbuf,    g_act);
    cudaGetSymbolAddress((void**)&alphab,    g_alpha);
    cudaGetSymbolAddress((void**)&degb,      g_deg);
    cudaGetSymbolAddress((void**)&rowstartb, g_rowstart);
    cudaGetSymbolAddress((void**)&cursorb,   g_cursor);
    cudaGetSymbolAddress((void**)&csrsrcb,   g_csr_src);
    cudaGetSymbolAddress((void**)&coefb,     g_coef);
    cudaGetSymbolAddress((void**)&poolb,     g_pool);
    cudaGetSymbolAddress((void**)&cntb,      g_cnt);

    float* node_emb  = (float*)d_out;
    float* graph_emb = (float*)d_out + (size_t)n * HID;

    // ---- CSR build (once, shared by all 3 layers) ----
    cudaMemsetAsync(degb, 0, (size_t)n * sizeof(int));
    deg_kernel<<<(E + 255) / 256, 256>>>(dst, degb, E);
    scan_kernel<<<1, 1024>>>(degb, rowstartb, n);
    cudaMemcpyAsync(cursorb, rowstartb, (size_t)n * sizeof(int), cudaMemcpyDeviceToDevice);
    csr_scatter_kernel<<<(E + 255) / 256, 256>>>(src, dst, cursorb, csrsrcb, E);

    // ---- layers ----
    run_gat_layer(x, FIN, W1, a1s, a1d, b1, HEADS, actbuf, 1,
                  n, rowstartb, csrsrcb, hbuf, alphab, coefb);
    run_gat_layer(actbuf, HEADS * HID, W2, a2s, a2d, b2, HEADS, actbuf, 1,
                  n, rowstartb, csrsrcb, hbuf, alphab, coefb);
    run_gat_layer(actbuf, HEADS * HID, W3, a3s, a3d, b3, 1, node_emb, 0,
                  n, rowstartb, csrsrcb, hbuf, alphab, coefb);

    // ---- global mean pool ----
    cudaMemsetAsync(poolb, 0, NGRAPH * HID * sizeof(float));
    cudaMemsetAsync(cntb, 0, NGRAPH * sizeof(float));
    pool_sum_kernel<<<n, HID>>>(node_emb, batch, poolb, cntb, n);
    pool_div_kernel<<<(NGRAPH * HID + 127) / 128, 128>>>(poolb, cntb, graph_emb);
}

// round 9
// speedup vs baseline: 1.1647x; 1.0230x over previous
#include <cuda_runtime.h>
#include <cuda_fp16.h>
#include <cstdint>
#include <cstddef>

#define NN 50000
#define EE 800000
#define FIN 256
#define HID 128
#define HEADS 4
#define NGRAPH 50
#define NEG_SLOPE 0.2f

// ---------------- scratch (device globals; no allocation allowed) -------------
__device__ __half g_hh[(size_t)NN * HEADS * HID];   // GEMM output (fp16 messages)
__device__ float g_act[(size_t)NN * HEADS * HID];   // aggregated output / next input
__device__ float g_alpha[2 * NN * HEADS];           // [0]=as, [NN*HEADS]=ad
__device__ int   g_deg[NN];
__device__ int   g_rowstart[NN + 1];
__device__ int   g_cursor[NN];
__device__ int   g_csr_src[EE];
__device__ float g_pool[NGRAPH * HID];
__device__ float g_cnt[NGRAPH];

// ==================== TF32 tensor-core GEMM + fused alpha epilogue ====================
// C[M,N] = A[M,K] @ B[K,N]; C stored fp16. Each 128-col block tile covers one
// head; per-row alpha dots are reduced across the 4 n-warps in smem and stored
// directly (no atomics, no memset needed).
__device__ __forceinline__ float to_tf32(float x) {
    float y;
    asm("cvt.rna.tf32.f32 %0, %1;" : "=f"(y) : "f"(x));
    return y;
}

__global__ __launch_bounds__(256) void tf32_gemm_alpha_kernel(
    const float* __restrict__ A, const float* __restrict__ B, __half* __restrict__ C,
    int M, int K, int N,
    const float* __restrict__ a_src, const float* __restrict__ a_dst,  // [H][HID]
    float* __restrict__ as_out, float* __restrict__ ad_out, int H)
{
    __shared__ __align__(16) float As[128][36];
    __shared__ __align__(16) float Bs[32][136];

    const int tid  = threadIdx.x;
    const int lane = tid & 31;
    const int warp = tid >> 5;
    const int wm = (warp & 1) * 64;
    const int wn = (warp >> 1) * 32;
    const int wnIdx = warp >> 1;

    const int mBase = blockIdx.y * 128;
    const int nBase = blockIdx.x * 128;

    float c[4][4][4];
#pragma unroll
    for (int mi = 0; mi < 4; mi++)
#pragma unroll
        for (int ni = 0; ni < 4; ni++)
#pragma unroll
            for (int q = 0; q < 4; q++) c[mi][ni][q] = 0.f;

    const int arow = tid >> 3;
    const int acol = (tid & 7) * 4;
    const int brow = tid >> 5;
    const int bcol = (tid & 31) * 4;

    for (int k0 = 0; k0 < K; k0 += 32) {
#pragma unroll
        for (int p = 0; p < 4; p++) {
            int r = arow + p * 32;
            int gr = mBase + r;
            float4 v = make_float4(0.f, 0.f, 0.f, 0.f);
            if (gr < M) v = *(const float4*)&A[(size_t)gr * K + k0 + acol];
            As[r][acol + 0] = to_tf32(v.x);
            As[r][acol + 1] = to_tf32(v.y);
            As[r][acol + 2] = to_tf32(v.z);
            As[r][acol + 3] = to_tf32(v.w);
        }
#pragma unroll
        for (int p = 0; p < 4; p++) {
            int r = brow + p * 8;
            float4 v = *(const float4*)&B[(size_t)(k0 + r) * N + nBase + bcol];
            Bs[r][bcol + 0] = to_tf32(v.x);
            Bs[r][bcol + 1] = to_tf32(v.y);
            Bs[r][bcol + 2] = to_tf32(v.z);
            Bs[r][bcol + 3] = to_tf32(v.w);
        }
        __syncthreads();

#pragma unroll
        for (int kk = 0; kk < 32; kk += 8) {
            uint32_t a[4][4], b[4][2];
            const int g = lane >> 2;
            const int l = lane & 3;
#pragma unroll
            for (int mi = 0; mi < 4; mi++) {
                int r = wm + mi * 16 + g;
                a[mi][0] = __float_as_uint(As[r][kk + l]);
                a[mi][1] = __float_as_uint(As[r + 8][kk + l]);
                a[mi][2] = __float_as_uint(As[r][kk + l + 4]);
                a[mi][3] = __float_as_uint(As[r + 8][kk + l + 4]);
            }
#pragma unroll
            for (int ni = 0; ni < 4; ni++) {
                int ncol = wn + ni * 8 + g;
                b[ni][0] = __float_as_uint(Bs[kk + l][ncol]);
                b[ni][1] = __float_as_uint(Bs[kk + l + 4][ncol]);
            }
#pragma unroll
            for (int mi = 0; mi < 4; mi++)
#pragma unroll
                for (int ni = 0; ni < 4; ni++) {
                    asm volatile(
                        "mma.sync.aligned.m16n8k8.row.col.f32.tf32.tf32.f32 "
                        "{%0,%1,%2,%3}, {%4,%5,%6,%7}, {%8,%9}, {%0,%1,%2,%3};\n"
                        : "+f"(c[mi][ni][0]), "+f"(c[mi][ni][1]),
                          "+f"(c[mi][ni][2]), "+f"(c[mi][ni][3])
                        : "r"(a[mi][0]), "r"(a[mi][1]), "r"(a[mi][2]), "r"(a[mi][3]),
                          "r"(b[ni][0]), "r"(b[ni][1]));
                }
        }
        __syncthreads();
    }

    const int g = lane >> 2;
    const int l = lane & 3;
    const int hh = nBase / HID;

    // repurpose As smem for the alpha reduction: [128 rows][4 wn][2 (s,d)]
    float* s_red = &As[0][0];

#pragma unroll
    for (int mi = 0; mi < 4; mi++) {
        int r0 = mBase + wm + mi * 16 + g;
        int r1 = r0 + 8;
        float ps0 = 0.f, pd0 = 0.f, ps1 = 0.f, pd1 = 0.f;
#pragma unroll
        for (int ni = 0; ni < 4; ni++) {
            int col = nBase + wn + ni * 8 + 2 * l;
            if (r0 < M)
                *(__half2*)&C[(size_t)r0 * N + col] =
                    __float22half2_rn(make_float2(c[mi][ni][0], c[mi][ni][1]));
            if (r1 < M)
                *(__half2*)&C[(size_t)r1 * N + col] =
                    __float22half2_rn(make_float2(c[mi][ni][2], c[mi][ni][3]));
            int cc = wn + ni * 8 + 2 * l;
            float sa0 = a_src[hh * HID + cc],     sa1 = a_src[hh * HID + cc + 1];
            float da0 = a_dst[hh * HID + cc],     da1 = a_dst[hh * HID + cc + 1];
            ps0 += c[mi][ni][0] * sa0 + c[mi][ni][1] * sa1;
            pd0 += c[mi][ni][0] * da0 + c[mi][ni][1] * da1;
            ps1 += c[mi][ni][2] * sa0 + c[mi][ni][3] * sa1;
            pd1 += c[mi][ni][2] * da0 + c[mi][ni][3] * da1;
        }
#pragma unroll
        for (int o = 1; o <= 2; o <<= 1) {
            ps0 += __shfl_xor_sync(0xffffffffu, ps0, o);
            pd0 += __shfl_xor_sync(0xffffffffu, pd0, o);
            ps1 += __shfl_xor_sync(0xffffffffu, ps1, o);
            pd1 += __shfl_xor_sync(0xffffffffu, pd1, o);
        }
        if (l == 0) {
            int lr0 = wm + mi * 16 + g;
            s_red[(lr0)     * 8 + wnIdx * 2 + 0] = ps0;
            s_red[(lr0)     * 8 + wnIdx * 2 + 1] = pd0;
            s_red[(lr0 + 8) * 8 + wnIdx * 2 + 0] = ps1;
            s_red[(lr0 + 8) * 8 + wnIdx * 2 + 1] = pd1;
        }
    }
    __syncthreads();
    if (tid < 128) {
        int gr = mBase + tid;
        if (gr < M) {
            float as = s_red[tid * 8 + 0] + s_red[tid * 8 + 2] +
                       s_red[tid * 8 + 4] + s_red[tid * 8 + 6];
            float ad = s_red[tid * 8 + 1] + s_red[tid * 8 + 3] +
                       s_red[tid * 8 + 5] + s_red[tid * 8 + 7];
            as_out[gr * H + hh] = as;
            ad_out[gr * H + hh] = ad;
        }
    }
}

// ==================== CSR build ====================
__global__ void deg_kernel(const int* __restrict__ dst, int* __restrict__ deg, int E)
{
    int e = blockIdx.x * blockDim.x + threadIdx.x;
    if (e < E) atomicAdd(&deg[dst[e]], 1);
}

__global__ __launch_bounds__(1024) void scan_kernel(const int* __restrict__ deg,
                                                    int* __restrict__ rowstart, int n)
{
    __shared__ int warp_sums[32];
    __shared__ int s_carry;
    int t = threadIdx.x;
    int lane = t & 31, w = t >> 5;
    if (t == 0) s_carry = 0;
    __syncthreads();
    for (int base = 0; base < n; base += 1024) {
        int i = base + t;
        int x = (i < n) ? deg[i] : 0;
        int v = x;
#pragma unroll
        for (int o = 1; o < 32; o <<= 1) {
            int y = __shfl_up_sync(0xffffffffu, v, o);
            if (lane >= o) v += y;
        }
        if (lane == 31) warp_sums[w] = v;
        __syncthreads();
        if (w == 0) {
            int s = warp_sums[lane];
#pragma unroll
            for (int o = 1; o < 32; o <<= 1) {
                int y = __shfl_up_sync(0xffffffffu, s, o);
                if (lane >= o) s += y;
            }
            warp_sums[lane] = s;
        }
        __syncthreads();
        int prefix = s_carry + (w > 0 ? warp_sums[w - 1] : 0) + v - x;
        if (i < n) rowstart[i] = prefix;
        __syncthreads();
        if (t == 0) s_carry += warp_sums[31];
        __syncthreads();
    }
    if (t == 0) rowstart[n] = s_carry;
}

__global__ void csr_scatter_kernel(const int* __restrict__ src, const int* __restrict__ dst,
                                   int* __restrict__ cursor, int* __restrict__ csr_src, int E)
{
    int e = blockIdx.x * blockDim.x + threadIdx.x;
    if (e >= E) return;
    int p = atomicAdd(&cursor[dst[e]], 1);
    csr_src[p] = src[e];
}

// ==================== FUSED softmax + aggregate + bias + ELU (warp per node) ====================
// Lane j gathers as_[src_j] once, computes the softmax coefficient in registers,
// parks (src, coef) in smem, then the warp streams the fp16 message gather.
template <int H>
__global__ __launch_bounds__(256) void gat_fused_kernel(
    const int* __restrict__ rowstart, const int* __restrict__ csr_src,
    const float* __restrict__ as_, const float* __restrict__ ad_,
    const __half* __restrict__ hbuf, const float* __restrict__ bias,
    float* __restrict__ out, int do_elu, int n)
{
    __shared__ int   s_src[8][32];
    __shared__ float s_cf[8][32][H];

    const int w = threadIdx.x >> 5;
    const int lane = threadIdx.x & 31;
    const int d = blockIdx.x * 8 + w;
    if (d >= n) return;
    const int e0 = rowstart[d];
    const int deg = rowstart[d + 1] - e0;
    const int W = H * HID;
    const int CH = (H == 4) ? 16 : 4;
    const int c0 = lane * CH;
    const int hd = (H == 4) ? (lane >> 3) : 0;
    const float NEG_INF = -__int_as_float(0x7f800000);

    float adv[H];
#pragma unroll
    for (int h = 0; h < H; h++) adv[h] = ad_[d * H + h];

    float acc[16];
#pragma unroll
    for (int i = 0; i < CH; i++) acc[i] = 0.f;

    if (deg <= 32) {
        // ---------- fast path: one edge per lane, single gather ----------
        bool valid = lane < deg;
        int s = 0;
        float v[H];
        if (valid) {
            s = __ldg(&csr_src[e0 + lane]);
            if (H == 4) {
                float4 av = __ldg((const float4*)&as_[s * 4]);
                v[0] = av.x + adv[0]; v[1] = av.y + adv[1];
                v[2] = av.z + adv[2]; v[3] = av.w + adv[3];
            } else {
                v[0] = __ldg(&as_[s]) + adv[0];
            }
#pragma unroll
            for (int h = 0; h < H; h++) v[h] = (v[h] >= 0.f) ? v[h] : NEG_SLOPE * v[h];
        } else {
#pragma unroll
            for (int h = 0; h < H; h++) v[h] = NEG_INF;
        }
#pragma unroll
        for (int h = 0; h < H; h++) {
            float mx = v[h];
#pragma unroll
            for (int o = 16; o; o >>= 1)
                mx = fmaxf(mx, __shfl_xor_sync(0xffffffffu, mx, o));
            float e = valid ? expf(v[h] - mx) : 0.f;
            float sm = e;
#pragma unroll
            for (int o = 16; o; o >>= 1)
                sm += __shfl_xor_sync(0xffffffffu, sm, o);
            v[h] = e / (sm + 1e-16f);
        }
        s_src[w][lane] = s;
#pragma unroll
        for (int h = 0; h < H; h++) s_cf[w][lane][h] = v[h];
        __syncwarp();

#pragma unroll 4
        for (int j = 0; j < deg; j++) {
            int sj = s_src[w][j];
            float cf = s_cf[w][j][hd];
            const __half* hp = hbuf + (size_t)sj * W + c0;
            if (H == 4) {
                uint4 r0 = __ldg((const uint4*)hp);
                uint4 r1 = __ldg((const uint4*)(hp + 8));
                const __half2* p0 = (const __half2*)&r0;
                const __half2* p1 = (const __half2*)&r1;
#pragma unroll
                for (int q = 0; q < 4; q++) {
                    float2 f0 = __half22float2(p0[q]);
                    float2 f1 = __half22float2(p1[q]);
                    acc[2 * q + 0] += f0.x * cf;
                    acc[2 * q + 1] += f0.y * cf;
                    acc[8 + 2 * q + 0] += f1.x * cf;
                    acc[8 + 2 * q + 1] += f1.y * cf;
                }
            } else {
                uint2 r0 = __ldg((const uint2*)hp);
                const __half2* p0 = (const __half2*)&r0;
#pragma unroll
                for (int q = 0; q < 2; q++) {
                    float2 f0 = __half22float2(p0[q]);
                    acc[2 * q + 0] += f0.x * cf;
                    acc[2 * q + 1] += f0.y * cf;
                }
            }
        }
    } else {
        // ---------- generic path: 2-pass softmax stats, then chunked aggregate ----------
        float mx[H], sm[H];
#pragma unroll
        for (int h = 0; h < H; h++) { mx[h] = NEG_INF; sm[h] = 0.f; }
        for (int j = lane; j < deg; j += 32) {
            int s = __ldg(&csr_src[e0 + j]);
#pragma unroll
            for (int h = 0; h < H; h++) {
                float v = as_[s * H + h] + adv[h];
                v = (v >= 0.f) ? v : NEG_SLOPE * v;
                mx[h] = fmaxf(mx[h], v);
            }
        }
#pragma unroll
        for (int h = 0; h < H; h++)
#pragma unroll
            for (int o = 16; o; o >>= 1)
                mx[h] = fmaxf(mx[h], __shfl_xor_sync(0xffffffffu, mx[h], o));
        for (int j = lane; j < deg; j += 32) {
            int s = __ldg(&csr_src[e0 + j]);
#pragma unroll
            for (int h = 0; h < H; h++) {
                float v = as_[s * H + h] + adv[h];
                v = (v >= 0.f) ? v : NEG_SLOPE * v;
                sm[h] += expf(v - mx[h]);
            }
        }
        float inv[H];
#pragma unroll
        for (int h = 0; h < H; h++) {
#pragma unroll
            for (int o = 16; o; o >>= 1)
                sm[h] += __shfl_xor_sync(0xffffffffu, sm[h], o);
            inv[h] = 1.f / (sm[h] + 1e-16f);
        }

        for (int base = 0; base < deg; base += 32) {
            int j = base + lane;
            bool valid = j < deg;
            int s = 0;
            float cf[H];
            if (valid) {
                s = __ldg(&csr_src[e0 + j]);
#pragma unroll
                for (int h = 0; h < H; h++) {
                    float v = as_[s * H + h] + adv[h];
                    v = (v >= 0.f) ? v : NEG_SLOPE * v;
                    cf[h] = expf(v - mx[h]) * inv[h];
                }
            } else {
#pragma unroll
                for (int h = 0; h < H; h++) cf[h] = 0.f;
            }
            __syncwarp();
            s_src[w][lane] = s;
#pragma unroll
            for (int h = 0; h < H; h++) s_cf[w][lane][h] = cf[h];
            __syncwarp();

            int nn = min(32, deg - base);
#pragma unroll 4
            for (int jj = 0; jj < nn; jj++) {
                int sj = s_src[w][jj];
                float c = s_cf[w][jj][hd];
                const __half* hp = hbuf + (size_t)sj * W + c0;
                if (H == 4) {
                    uint4 r0 = __ldg((const uint4*)hp);
                    uint4 r1 = __ldg((const uint4*)(hp + 8));
                    const __half2* p0 = (const __half2*)&r0;
                    const __half2* p1 = (const __half2*)&r1;
#pragma unroll
                    for (int q = 0; q < 4; q++) {
                        float2 f0 = __half22float2(p0[q]);
                        float2 f1 = __half22float2(p1[q]);
                        acc[2 * q + 0] += f0.x * c;
                        acc[2 * q + 1] += f0.y * c;
                        acc[8 + 2 * q + 0] += f1.x * c;
                        acc[8 + 2 * q + 1] += f1.y * c;
                    }
                } else {
                    uint2 r0 = __ldg((const uint2*)hp);
                    const __half2* p0 = (const __half2*)&r0;
#pragma unroll
                    for (int q = 0; q < 2; q++) {
                        float2 f0 = __half22float2(p0[q]);
                        acc[2 * q + 0] += f0.x * c;
                        acc[2 * q + 1] += f0.y * c;
                    }
                }
            }
        }
    }

    // epilogue: bias + optional ELU
#pragma unroll
    for (int i = 0; i < CH; i += 4) {
        float4 b = *(const float4*)&bias[c0 + i];
        float v0 = acc[i + 0] + b.x, v1 = acc[i + 1] + b.y;
        float v2 = acc[i + 2] + b.z, v3 = acc[i + 3] + b.w;
        if (do_elu) {
            v0 = (v0 > 0.f) ? v0 : expm1f(v0);
            v1 = (v1 > 0.f) ? v1 : expm1f(v1);
            v2 = (v2 > 0.f) ? v2 : expm1f(v2);
            v3 = (v3 > 0.f) ? v3 : expm1f(v3);
        }
        *(float4*)&out[(size_t)d * W + c0 + i] = make_float4(v0, v1, v2, v3);
    }
}

// ==================== pooling ====================
__global__ void pool_sum_kernel(const float* __restrict__ node_emb, const int* __restrict__ batch,
                                float* __restrict__ pool, float* __restrict__ cnt, int n)
{
    int node = blockIdx.x;
    int t = threadIdx.x;
    int g = batch[node];
    atomicAdd(&pool[g * HID + t], node_emb[(size_t)node * HID + t]);
    if (t == 0) atomicAdd(&cnt[g], 1.0f);
}

__global__ void pool_div_kernel(const float* __restrict__ pool, const float* __restrict__ cnt,
                                float* __restrict__ out)
{
    int i = blockIdx.x * blockDim.x + threadIdx.x;
    if (i >= NGRAPH * HID) return;
    int g = i / HID;
    out[i] = pool[i] / fmaxf(cnt[g], 1.0f);
}

// ==================== host side ====================
static void run_gat_layer(const float* in, int fin,
                          const float* W, const float* a_s, const float* a_d, const float* bias,
                          int heads, float* out, int do_elu,
                          int n, const int* rowstart, const int* csr_src,
                          __half* hbuf, float* alphab)
{
    const int width = heads * HID;
    float* asb = alphab;
    float* adb = alphab + NN * HEADS;

    dim3 ggrid(width / 128, (n + 127) / 128);
    tf32_gemm_alpha_kernel<<<ggrid, 256>>>(in, W, hbuf, n, fin, width,
                                           a_s, a_d, asb, adb, heads);

    int wgrid = (n + 7) / 8;
    if (heads == 4)
        gat_fused_kernel<4><<<wgrid, 256>>>(rowstart, csr_src, asb, adb, hbuf, bias, out, do_elu, n);
    else
        gat_fused_kernel<1><<<wgrid, 256>>>(rowstart, csr_src, asb, adb, hbuf, bias, out, do_elu, n);
}

extern "C" void kernel_launch(void* const* d_in, const int* in_sizes, int n_in,
                              void* d_out, int out_size)
{
    const float* x     = (const float*)d_in[0];
    const int*   ei    = (const int*)d_in[1];
    const int*   batch = (const int*)d_in[2];
    const float* W1  = (const float*)d_in[3];
    const float* a1s = (const float*)d_in[4];
    const float* a1d = (const float*)d_in[5];
    const float* b1  = (const float*)d_in[6];
    const float* W2  = (const float*)d_in[7];
    const float* a2s = (const float*)d_in[8];
    const float* a2d = (const float*)d_in[9];
    const float* b2  = (const float*)d_in[10];
    const float* W3  = (const float*)d_in[11];
    const float* a3s = (const float*)d_in[12];
    const float* a3d = (const float*)d_in[13];
    const float* b3  = (const float*)d_in[14];

    const int n = in_sizes[0] / FIN;
    const int E = in_sizes[1] / 2;
    const int* src = ei;
    const int* dst = ei + E;

    float *actbuf, *alphab, *poolb, *cntb;
    __half* hbuf;
    int *degb, *rowstartb, *cursorb, *csrsrcb;
    cudaGetSymbolAddress((void**)&hbuf,      g_hh);
    cudaGetSymbolAddress((void**)&actbuf,    g_act);
    cudaGetSymbolAddress((void**)&alphab,    g_alpha);
    cudaGetSymbolAddress((void**)&degb,      g_deg);
    cudaGetSymbolAddress((void**)&rowstartb, g_rowstart);
    cudaGetSymbolAddress((void**)&cursorb,   g_cursor);
    cudaGetSymbolAddress((void**)&csrsrcb,   g_csr_src);
    cudaGetSymbolAddress((void**)&poolb,     g_pool);
    cudaGetSymbolAddress((void**)&cntb,      g_cnt);

    float* node_emb  = (float*)d_out;
    float* graph_emb = (float*)d_out + (size_t)n * HID;

    // ---- CSR build (once, shared by all 3 layers) ----
    cudaMemsetAsync(degb, 0, (size_t)n * sizeof(int));
    deg_kernel<<<(E + 255) / 256, 256>>>(dst, degb, E);
    scan_kernel<<<1, 1024>>>(degb, rowstartb, n);
    cudaMemcpyAsync(cursorb, rowstartb, (size_t)n * sizeof(int), cudaMemcpyDeviceToDevice);
    csr_scatter_kernel<<<(E + 255) / 256, 256>>>(src, dst, cursorb, csrsrcb, E);

    // ---- layers ----
    run_gat_layer(x, FIN, W1, a1s, a1d, b1, HEADS, actbuf, 1,
                  n, rowstartb, csrsrcb, hbuf, alphab);
    run_gat_layer(actbuf, HEADS * HID, W2, a2s, a2d, b2, HEADS, actbuf, 1,
                  n, rowstartb, csrsrcb, hbuf, alphab);
    run_gat_layer(actbuf, HEADS * HID, W3, a3s, a3d, b3, 1, node_emb, 0,
                  n, rowstartb, csrsrcb, hbuf, alphab);

    // ---- global mean pool ----
    cudaMemsetAsync(poolb, 0, NGRAPH * HID * sizeof(float));
    cudaMemsetAsync(cntb, 0, NGRAPH * sizeof(float));
    pool_sum_kernel<<<n, HID>>>(node_emb, batch, poolb, cntb, n);
    pool_div_kernel<<<(NGRAPH * HID + 127) / 128, 128>>>(poolb, cntb, graph_emb);
}